// round 4
// baseline (speedup 1.0000x reference)
#include <cuda_runtime.h>

#define DIM 128
#define NROWS 2048
#define DK 16
#define NCHUNK (DIM / DK)
#define BR 64        // rows per CTA tile
#define BC 128       // cols per CTA tile

typedef unsigned long long ull;

// d-major scratch. A is stored DUPLICATED: g_At2[d][2n] = g_At2[d][2n+1] = hi[n,d]
__device__ __align__(128) float g_At2[DIM * 2 * NROWS];   // 2MB
__device__ __align__(128) float g_Ct[DIM * NROWS];        // 1MB

// ---------------------------------------------------------------------------
// Precompute. side 0 -> At2[d][2n]={hi,hi},  side 1 -> Ct[d][m] = hj + b1
// grid (128, 2), block 256: 16 rows x 128 d per block; thread: 1 row x 8 d.
// ---------------------------------------------------------------------------
__global__ void precompute_kernel(const float* __restrict__ z_i,
                                  const float* __restrict__ z_j,
                                  const float* __restrict__ W1,
                                  const float* __restrict__ b1) {
    __shared__ __align__(16) float Zs[16][DIM];    // 8KB
    __shared__ __align__(16) float W1s[32][DIM];   // 16KB (k-chunk)

    const int side = blockIdx.y;
    const float* z  = (side == 0) ? z_i : z_j;
    const float* w1 = W1 + side * DIM * DIM;
    const int rowBase = blockIdx.x * 16;
    const int tid = threadIdx.x;

    // load Zs: 16 rows x 128 = 512 float4 / 256 threads
    #pragma unroll
    for (int l = 0; l < 2; l++) {
        int idx = tid + 256 * l;
        int r = idx >> 5, c4 = idx & 31;
        float4 v = ((const float4*)(z + (size_t)(rowBase + r) * DIM))[c4];
        *(float4*)&Zs[r][c4 * 4] = v;
    }

    const int dg = (tid & 15) * 8;   // 8 d-outputs
    const int ng = tid >> 4;         // 1 row

    float acc[8];
    #pragma unroll
    for (int j = 0; j < 8; j++) acc[j] = 0.f;

    for (int k0 = 0; k0 < DIM; k0 += 32) {
        __syncthreads();
        #pragma unroll
        for (int l = 0; l < 4; l++) {
            int idx = tid + 256 * l;
            int r = idx >> 5, c4 = idx & 31;
            float4 v = ((const float4*)(w1 + (size_t)(k0 + r) * DIM))[c4];
            *(float4*)&W1s[r][c4 * 4] = v;
        }
        __syncthreads();
        #pragma unroll
        for (int kk = 0; kk < 32; kk++) {
            float4 wa = *(const float4*)&W1s[kk][dg];
            float4 wb = *(const float4*)&W1s[kk][dg + 4];
            float zv = Zs[ng][k0 + kk];
            acc[0] = fmaf(zv, wa.x, acc[0]);
            acc[1] = fmaf(zv, wa.y, acc[1]);
            acc[2] = fmaf(zv, wa.z, acc[2]);
            acc[3] = fmaf(zv, wa.w, acc[3]);
            acc[4] = fmaf(zv, wb.x, acc[4]);
            acc[5] = fmaf(zv, wb.y, acc[5]);
            acc[6] = fmaf(zv, wb.z, acc[6]);
            acc[7] = fmaf(zv, wb.w, acc[7]);
        }
    }

    const int n = rowBase + ng;
    if (side == 0) {
        #pragma unroll
        for (int j = 0; j < 8; j++)
            *(float2*)&g_At2[(size_t)(dg + j) * (2 * NROWS) + 2 * n] =
                make_float2(acc[j], acc[j]);
    } else {
        #pragma unroll
        for (int j = 0; j < 8; j++)
            g_Ct[(size_t)(dg + j) * NROWS + n] = acc[j] + b1[dg + j];
    }
}

// ---------------------------------------------------------------------------
// cp.async helpers
// ---------------------------------------------------------------------------
__device__ __forceinline__ void cpa16(void* smem_dst, const void* gmem_src) {
    unsigned s = (unsigned)__cvta_generic_to_shared(smem_dst);
    asm volatile("cp.async.cg.shared.global [%0], [%1], 16;\n"
                 :: "r"(s), "l"(gmem_src));
}
#define CP_COMMIT() asm volatile("cp.async.commit_group;\n" ::: "memory")
#define CP_WAIT0()  asm volatile("cp.async.wait_group 0;\n" ::: "memory")

// ---------------------------------------------------------------------------
// Main: out[n,m] = sum_d relu(A[d][n] + C[d][m]) * w2[d] + b2
// Tile 64x128, 256 threads, per-thread 4 rows x 4 col-pairs (16 pairs).
// cp.async double-buffered smem. Per pair: add.f32x2 + 2xFMNMX + fma.f32x2.
// ---------------------------------------------------------------------------
__global__ void __launch_bounds__(256, 3)
mlp_score_kernel(const float* __restrict__ W2, const float* __restrict__ b2p,
                 float* __restrict__ out) {
    __shared__ __align__(16) float As[2][DK][2 * BR];  // dup pairs, 16KB
    __shared__ __align__(16) float Cs[2][DK][BC];      // 16KB
    __shared__ __align__(8)  float Ws[DIM][2];         // dup w2, 1KB

    const int tid = threadIdx.x;
    const int tc = tid & 15;        // col group: 4 pairs = 8 cols
    const int tr = tid >> 4;        // row group: 4 rows
    const int rowBase = blockIdx.y * BR;
    const int colBase = blockIdx.x * BC;

    // staging decomposition: A chunk = 16x128 floats = 512 f4; C same.
    const int sdA = tid >> 5;             // d 0..7 (l=0), +8 for l=1
    const int sf4 = tid & 31;             // float4 index in 128-float row

    // W2 duplicated into smem (once)
    if (tid < DIM) {
        float w = W2[tid];
        Ws[tid][0] = w; Ws[tid][1] = w;
    }

    // prologue: stage chunk 0 into buffer 0
    {
        const float* a0 = &g_At2[(size_t)sdA * (2 * NROWS) + 2 * rowBase + sf4 * 4];
        const float* a1 = &g_At2[(size_t)(sdA + 8) * (2 * NROWS) + 2 * rowBase + sf4 * 4];
        const float* c0 = &g_Ct[(size_t)sdA * NROWS + colBase + sf4 * 4];
        const float* c1 = &g_Ct[(size_t)(sdA + 8) * NROWS + colBase + sf4 * 4];
        cpa16(&As[0][sdA][sf4 * 4], a0);
        cpa16(&As[0][sdA + 8][sf4 * 4], a1);
        cpa16(&Cs[0][sdA][sf4 * 4], c0);
        cpa16(&Cs[0][sdA + 8][sf4 * 4], c1);
        CP_COMMIT();
    }

    const float b2 = __ldg(b2p);
    ull binit;
    asm("mov.b64 %0, {%1, %1};" : "=l"(binit) : "f"(b2));

    ull acc[4][4];
    #pragma unroll
    for (int i = 0; i < 4; i++)
        #pragma unroll
        for (int j = 0; j < 4; j++) acc[i][j] = binit;

    for (int c = 0; c < NCHUNK; c++) {
        const int buf = c & 1;
        const int nbuf = buf ^ 1;

        CP_WAIT0();          // chunk c landed
        __syncthreads();     // visible to all; prior compute done

        // stage chunk c+1 (overlaps compute below)
        if (c + 1 < NCHUNK) {
            const size_t dn = (size_t)(c + 1) * DK;
            cpa16(&As[nbuf][sdA][sf4 * 4],
                  &g_At2[(dn + sdA) * (2 * NROWS) + 2 * rowBase + sf4 * 4]);
            cpa16(&As[nbuf][sdA + 8][sf4 * 4],
                  &g_At2[(dn + sdA + 8) * (2 * NROWS) + 2 * rowBase + sf4 * 4]);
            cpa16(&Cs[nbuf][sdA][sf4 * 4],
                  &g_Ct[(dn + sdA) * NROWS + colBase + sf4 * 4]);
            cpa16(&Cs[nbuf][sdA + 8][sf4 * 4],
                  &g_Ct[(dn + sdA + 8) * NROWS + colBase + sf4 * 4]);
            CP_COMMIT();
        }

        #pragma unroll 2
        for (int d = 0; d < DK; d++) {
            ull w2 = *(const ull*)&Ws[c * DK + d][0];

            ull a2[4], c2[4];
            {
                const ulonglong2* ap = (const ulonglong2*)&As[buf][d][8 * tr];
                ulonglong2 v0 = ap[0], v1 = ap[1];
                a2[0] = v0.x; a2[1] = v0.y; a2[2] = v1.x; a2[3] = v1.y;
                const ulonglong2* cp = (const ulonglong2*)&Cs[buf][d][8 * tc];
                ulonglong2 u0 = cp[0], u1 = cp[1];
                c2[0] = u0.x; c2[1] = u0.y; c2[2] = u1.x; c2[3] = u1.y;
            }
            #pragma unroll
            for (int i = 0; i < 4; i++) {
                #pragma unroll
                for (int j = 0; j < 4; j++) {
                    ull t, r;
                    asm("add.rn.f32x2 %0, %1, %2;"
                        : "=l"(t) : "l"(a2[i]), "l"(c2[j]));
                    float lo, hi;
                    asm("mov.b64 {%0, %1}, %2;" : "=f"(lo), "=f"(hi) : "l"(t));
                    lo = fmaxf(lo, 0.f);
                    hi = fmaxf(hi, 0.f);
                    asm("mov.b64 %0, {%1, %2};" : "=l"(r) : "f"(lo), "f"(hi));
                    asm("fma.rn.f32x2 %0, %1, %2, %0;"
                        : "+l"(acc[i][j]) : "l"(r), "l"(w2));
                }
            }
        }
    }

    // epilogue (b2 folded into acc init)
    #pragma unroll
    for (int i = 0; i < 4; i++) {
        float* dst = &out[(size_t)(rowBase + tr * 4 + i) * NROWS + colBase + tc * 8];
        *(ulonglong2*)dst       = make_ulonglong2(acc[i][0], acc[i][1]);
        *(ulonglong2*)(dst + 4) = make_ulonglong2(acc[i][2], acc[i][3]);
    }
}

// ---------------------------------------------------------------------------
extern "C" void kernel_launch(void* const* d_in, const int* in_sizes, int n_in,
                              void* d_out, int out_size) {
    (void)in_sizes; (void)n_in; (void)out_size;
    const float* z_i = (const float*)d_in[0];
    const float* z_j = (const float*)d_in[1];
    const float* W1  = (const float*)d_in[2];
    const float* b1  = (const float*)d_in[3];
    const float* W2  = (const float*)d_in[4];
    const float* b2  = (const float*)d_in[5];
    float* out = (float*)d_out;

    precompute_kernel<<<dim3(128, 2), 256>>>(z_i, z_j, W1, b1);
    mlp_score_kernel<<<dim3(16, 32), 256>>>(W2, b2, out);
}

// round 5
// speedup vs baseline: 1.2508x; 1.2508x over previous
#include <cuda_runtime.h>

#define DIM 128
#define NROWS 2048
#define DK 16
#define NCHUNK (DIM / DK)
#define BR 128
#define BC 64
#define CPAD 20

typedef unsigned long long ull;

// row-major scratch, d contiguous: g_A[n][d] = hi ; g_C[m][d] = hj + b1
__device__ __align__(128) float g_A[NROWS * DIM];
__device__ __align__(128) float g_C[NROWS * DIM];

// ---------------------------------------------------------------------------
// Precompute: side 0 -> g_A[n][d] = z_i @ W1[:128]
//             side 1 -> g_C[m][d] = z_j @ W1[128:] + b1
// grid (64, 2), block 256: 32 rows x 128 d per block; thread 2 rows x 8 d.
// ---------------------------------------------------------------------------
__global__ void precompute_kernel(const float* __restrict__ z_i,
                                  const float* __restrict__ z_j,
                                  const float* __restrict__ W1,
                                  const float* __restrict__ b1) {
    __shared__ __align__(16) float Zs[32][DIM];
    __shared__ __align__(16) float W1s[32][DIM];

    const int side = blockIdx.y;
    const float* z  = side ? z_j : z_i;
    const float* w1 = W1 + side * DIM * DIM;
    const int rowBase = blockIdx.x * 32;
    const int tid = threadIdx.x;

    #pragma unroll
    for (int l = 0; l < 4; l++) {
        int idx = tid + 256 * l;
        int r = idx >> 5, c4 = idx & 31;
        float4 v = ((const float4*)(z + (size_t)(rowBase + r) * DIM))[c4];
        *(float4*)&Zs[r][c4 * 4] = v;
    }

    const int dg = (tid & 15) * 8;
    const int ng = (tid >> 4) * 2;

    float acc[2][8];
    #pragma unroll
    for (int i = 0; i < 2; i++)
        #pragma unroll
        for (int j = 0; j < 8; j++) acc[i][j] = 0.f;

    for (int k0 = 0; k0 < DIM; k0 += 32) {
        __syncthreads();
        #pragma unroll
        for (int l = 0; l < 4; l++) {
            int idx = tid + 256 * l;
            int r = idx >> 5, c4 = idx & 31;
            float4 v = ((const float4*)(w1 + (size_t)(k0 + r) * DIM))[c4];
            *(float4*)&W1s[r][c4 * 4] = v;
        }
        __syncthreads();
        #pragma unroll
        for (int kk = 0; kk < 32; kk++) {
            float4 wa = *(const float4*)&W1s[kk][dg];
            float4 wb = *(const float4*)&W1s[kk][dg + 4];
            float w[8] = {wa.x, wa.y, wa.z, wa.w, wb.x, wb.y, wb.z, wb.w};
            #pragma unroll
            for (int i = 0; i < 2; i++) {
                float zv = Zs[ng + i][k0 + kk];
                #pragma unroll
                for (int j = 0; j < 8; j++) acc[i][j] = fmaf(zv, w[j], acc[i][j]);
            }
        }
    }

    float* dst = side ? g_C : g_A;
    #pragma unroll
    for (int i = 0; i < 2; i++) {
        float o[8];
        #pragma unroll
        for (int j = 0; j < 8; j++)
            o[j] = side ? (acc[i][j] + b1[dg + j]) : acc[i][j];
        float* p = &dst[(size_t)(rowBase + ng + i) * DIM + dg];
        *(float4*)p       = make_float4(o[0], o[1], o[2], o[3]);
        *(float4*)(p + 4) = make_float4(o[4], o[5], o[6], o[7]);
    }
}

// ---------------------------------------------------------------------------
// cp.async helpers
// ---------------------------------------------------------------------------
__device__ __forceinline__ void cpa16(void* smem_dst, const void* gmem_src) {
    unsigned s = (unsigned)__cvta_generic_to_shared(smem_dst);
    asm volatile("cp.async.cg.shared.global [%0], [%1], 16;\n"
                 :: "r"(s), "l"(gmem_src));
}
#define CP_COMMIT() asm volatile("cp.async.commit_group;\n" ::: "memory")
#define CP_WAIT0()  asm volatile("cp.async.wait_group 0;\n" ::: "memory")

// ---------------------------------------------------------------------------
// Main: out[n,m] = sum_d relu(A[n,d] + C[m,d]) * w2[d] + b2
// d-pair packing: acc pair holds (sum over even d, sum over odd d); no
// operand duplication. Tile 128x64, thread 8 rows x 4 strided cols.
// ---------------------------------------------------------------------------
__global__ void __launch_bounds__(256, 2)
mlp_score_kernel(const float* __restrict__ W2, const float* __restrict__ b2p,
                 float* __restrict__ out) {
    __shared__ __align__(16) float As[2][BR][DK];    // 16KB
    __shared__ __align__(16) float Cs[2][BC][CPAD];  // 10KB
    __shared__ __align__(16) float Wsm[DIM];         // 0.5KB

    const int tid = threadIdx.x;
    const int tx = tid & 15;        // cols: tx + 16*j, j=0..3
    const int ty = tid >> 4;        // rows: ty*8 + i, i=0..7
    const int rowBase = blockIdx.y * BR;
    const int colBase = blockIdx.x * BC;

    if (tid < DIM / 4)
        ((float4*)Wsm)[tid] = ((const float4*)W2)[tid];

    // staging: A chunk = 128 rows x 4 f4 (512 f4); C chunk = 64 rows x 4 f4 (256 f4)
    const int arow = tid >> 1;       // 0..127
    const int af4  = tid & 1;        // f4 slot 0/1 (+2 for second)
    const int crow = tid >> 2;       // 0..63
    const int cf4  = tid & 3;

    // prologue: stage chunk 0
    cpa16(&As[0][arow][af4 * 4],
          &g_A[(size_t)(rowBase + arow) * DIM + af4 * 4]);
    cpa16(&As[0][arow][(af4 + 2) * 4],
          &g_A[(size_t)(rowBase + arow) * DIM + (af4 + 2) * 4]);
    cpa16(&Cs[0][crow][cf4 * 4],
          &g_C[(size_t)(colBase + crow) * DIM + cf4 * 4]);
    CP_COMMIT();

    const float b2 = __ldg(b2p);
    const float fz = 0.f;
    ull binit;
    asm("mov.b64 %0, {%1, %2};" : "=l"(binit) : "f"(b2), "f"(fz));

    ull acc[8][4];
    #pragma unroll
    for (int i = 0; i < 8; i++)
        #pragma unroll
        for (int j = 0; j < 4; j++) acc[i][j] = binit;

    for (int c = 0; c < NCHUNK; c++) {
        const int buf = c & 1;
        const int nbuf = buf ^ 1;

        CP_WAIT0();
        __syncthreads();

        if (c + 1 < NCHUNK) {
            const int dn = (c + 1) * DK;
            cpa16(&As[nbuf][arow][af4 * 4],
                  &g_A[(size_t)(rowBase + arow) * DIM + dn + af4 * 4]);
            cpa16(&As[nbuf][arow][(af4 + 2) * 4],
                  &g_A[(size_t)(rowBase + arow) * DIM + dn + (af4 + 2) * 4]);
            cpa16(&Cs[nbuf][crow][cf4 * 4],
                  &g_C[(size_t)(colBase + crow) * DIM + dn + cf4 * 4]);
            CP_COMMIT();
        }

        #pragma unroll
        for (int k = 0; k < 4; k++) {      // 4 d per k-step
            ulonglong2 av[8];
            ulonglong2 cv[4];
            #pragma unroll
            for (int i = 0; i < 8; i++)
                av[i] = *(const ulonglong2*)&As[buf][ty * 8 + i][k * 4];
            #pragma unroll
            for (int j = 0; j < 4; j++)
                cv[j] = *(const ulonglong2*)&Cs[buf][tx + 16 * j][k * 4];
            ull w0 = *(const ull*)&Wsm[c * DK + k * 4];
            ull w1 = *(const ull*)&Wsm[c * DK + k * 4 + 2];

            #pragma unroll
            for (int i = 0; i < 8; i++) {
                #pragma unroll
                for (int j = 0; j < 4; j++) {
                    ull t, r;
                    float lo, hi;
                    // pair (d, d+1)
                    asm("add.rn.f32x2 %0, %1, %2;"
                        : "=l"(t) : "l"(av[i].x), "l"(cv[j].x));
                    asm("mov.b64 {%0, %1}, %2;" : "=f"(lo), "=f"(hi) : "l"(t));
                    lo = fmaxf(lo, 0.f); hi = fmaxf(hi, 0.f);
                    asm("mov.b64 %0, {%1, %2};" : "=l"(r) : "f"(lo), "f"(hi));
                    asm("fma.rn.f32x2 %0, %1, %2, %0;"
                        : "+l"(acc[i][j]) : "l"(r), "l"(w0));
                    // pair (d+2, d+3)
                    asm("add.rn.f32x2 %0, %1, %2;"
                        : "=l"(t) : "l"(av[i].y), "l"(cv[j].y));
                    asm("mov.b64 {%0, %1}, %2;" : "=f"(lo), "=f"(hi) : "l"(t));
                    lo = fmaxf(lo, 0.f); hi = fmaxf(hi, 0.f);
                    asm("mov.b64 %0, {%1, %2};" : "=l"(r) : "f"(lo), "f"(hi));
                    asm("fma.rn.f32x2 %0, %1, %2, %0;"
                        : "+l"(acc[i][j]) : "l"(r), "l"(w1));
                }
            }
        }
    }

    // epilogue: out = acc.lo + acc.hi  (b2 folded into lo at init)
    #pragma unroll
    for (int i = 0; i < 8; i++) {
        const size_t rowOff = (size_t)(rowBase + ty * 8 + i) * NROWS + colBase;
        #pragma unroll
        for (int j = 0; j < 4; j++) {
            float lo, hi;
            asm("mov.b64 {%0, %1}, %2;" : "=f"(lo), "=f"(hi) : "l"(acc[i][j]));
            out[rowOff + tx + 16 * j] = lo + hi;
        }
    }
}

// ---------------------------------------------------------------------------
extern "C" void kernel_launch(void* const* d_in, const int* in_sizes, int n_in,
                              void* d_out, int out_size) {
    (void)in_sizes; (void)n_in; (void)out_size;
    const float* z_i = (const float*)d_in[0];
    const float* z_j = (const float*)d_in[1];
    const float* W1  = (const float*)d_in[2];
    const float* b1  = (const float*)d_in[3];
    const float* W2  = (const float*)d_in[4];
    const float* b2  = (const float*)d_in[5];
    float* out = (float*)d_out;

    precompute_kernel<<<dim3(64, 2), 256>>>(z_i, z_j, W1, b1);
    mlp_score_kernel<<<dim3(NROWS / BC, NROWS / BR), 256>>>(W2, b2, out);
}